// round 7
// baseline (speedup 1.0000x reference)
#include <cuda_runtime.h>
#include <cuda_bf16.h>
#include <cstdint>

// ---------------------------------------------------------------------------
// C[8192,4096] = A[8192,4096] * W[4096,4096]^T  (fp32 in/out)
// R7: bf16 3-term split GEMM (Markidis): a = ah + al (bf16 + bf16 residual),
//     C = Ah*Bh + Ah*Bl + Al*Bh  with fp32 accumulation via
//     mma.sync.m16n8k16.bf16 (2048 MACs/instr vs tf32's 1024).
// BM=256, BN=128, BK=32, 256 thr, warp tile 64x64, 3-stage cp.async,
// ldmatrix.x4 fragment loads. Error ~2^-16 per product -> rel_err ~2e-5.
// ---------------------------------------------------------------------------

#define MTOT 8192
#define KDIM 4096
#define NDIM 4096

#define BM 256
#define BN 128
#define BK 32
#define KITERS (KDIM / BK)        // 128
#define STAGES 3

// bf16 smem rows: 32 bf16 data padded to 40 bf16 (80 B) per row.
// 80 mod 128 walk: {0,80,32,112,64,16,96,48} -> ldmatrix conflict-free.
#define ROWB 80
#define AH_OFF 0
#define AL_OFF (256 * ROWB)            // 20480
#define BH_OFF (512 * ROWB)            // 40960
#define BL_OFF (BH_OFF + 128 * ROWB)   // 51200
#define STAGE_BYTES (768 * ROWB)       // 61440
#define SMEM_TOTAL (STAGES * STAGE_BYTES)  // 184320

// bf16 hi/lo scratch (device globals: allowed, no allocation)
__device__ __nv_bfloat16 g_Ah[(size_t)MTOT * KDIM];
__device__ __nv_bfloat16 g_Al[(size_t)MTOT * KDIM];
__device__ __nv_bfloat16 g_Wh[(size_t)NDIM * KDIM];
__device__ __nv_bfloat16 g_Wl[(size_t)NDIM * KDIM];

// ------------------------------- helpers -----------------------------------

__device__ __forceinline__ uint32_t smem_u32(const void* p) {
    uint32_t a;
    asm("{ .reg .u64 t; cvta.to.shared.u64 t, %1; cvt.u32.u64 %0, t; }"
        : "=r"(a) : "l"(p));
    return a;
}

__device__ __forceinline__ void cp_async16(uint32_t dst, const void* src) {
    asm volatile("cp.async.cg.shared.global [%0], [%1], 16;\n"
                 :: "r"(dst), "l"(src) : "memory");
}
__device__ __forceinline__ void cp_commit() {
    asm volatile("cp.async.commit_group;\n" ::: "memory");
}
__device__ __forceinline__ void cp_wait1() {
    asm volatile("cp.async.wait_group 1;\n" ::: "memory");
}

__device__ __forceinline__ void ldsm_x4(uint32_t& r0, uint32_t& r1,
                                        uint32_t& r2, uint32_t& r3,
                                        uint32_t addr) {
    asm volatile("ldmatrix.sync.aligned.m8n8.x4.shared.b16 {%0,%1,%2,%3}, [%4];"
                 : "=r"(r0), "=r"(r1), "=r"(r2), "=r"(r3) : "r"(addr));
}

__device__ __forceinline__ void mma_bf16(float* c, const uint32_t* a,
                                         const uint32_t* b) {
    asm volatile(
        "mma.sync.aligned.m16n8k16.row.col.f32.bf16.bf16.f32 "
        "{%0,%1,%2,%3}, {%4,%5,%6,%7}, {%8,%9}, {%0,%1,%2,%3};"
        : "+f"(c[0]), "+f"(c[1]), "+f"(c[2]), "+f"(c[3])
        : "r"(a[0]), "r"(a[1]), "r"(a[2]), "r"(a[3]),
          "r"(b[0]), "r"(b[1]));
}

// ------------------------------- prepass ------------------------------------
// Split fp32 into bf16 hi + bf16 lo residual. (float)hi is exact, the
// subtraction is exact, so al captures mantissa bits 8..15 -> product error
// ~2^-16 relative when the al*bl term is dropped.

__global__ void __launch_bounds__(256) prepass_kernel(const float* __restrict__ A,
                                                      const float* __restrict__ W) {
    const long long nA = (long long)MTOT * KDIM / 4;
    const long long nW = (long long)NDIM * KDIM / 4;
    const long long stride = (long long)gridDim.x * blockDim.x;
    for (long long i = (long long)blockIdx.x * blockDim.x + threadIdx.x;
         i < nA + nW; i += stride) {
        const float4* src;
        __nv_bfloat16 *dh, *dl;
        long long j;
        if (i < nA) { src = (const float4*)A; dh = g_Ah; dl = g_Al; j = i; }
        else        { src = (const float4*)W; dh = g_Wh; dl = g_Wl; j = i - nA; }
        float4 v = src[j];
        __nv_bfloat16 h0 = __float2bfloat16(v.x);
        __nv_bfloat16 h1 = __float2bfloat16(v.y);
        __nv_bfloat16 h2 = __float2bfloat16(v.z);
        __nv_bfloat16 h3 = __float2bfloat16(v.w);
        __nv_bfloat16 l0 = __float2bfloat16(v.x - __bfloat162float(h0));
        __nv_bfloat16 l1 = __float2bfloat16(v.y - __bfloat162float(h1));
        __nv_bfloat16 l2 = __float2bfloat16(v.z - __bfloat162float(h2));
        __nv_bfloat16 l3 = __float2bfloat16(v.w - __bfloat162float(h3));
        __nv_bfloat162* ph = (__nv_bfloat162*)(dh + 4 * j);
        __nv_bfloat162* pl = (__nv_bfloat162*)(dl + 4 * j);
        ph[0] = __nv_bfloat162(h0, h1);
        ph[1] = __nv_bfloat162(h2, h3);
        pl[0] = __nv_bfloat162(l0, l1);
        pl[1] = __nv_bfloat162(l2, l3);
    }
}

// ------------------------------- GEMM ---------------------------------------

__global__ void __launch_bounds__(256, 1) gemm_kernel(float* __restrict__ out) {
    extern __shared__ char smem[];
    const uint32_t sbase = smem_u32(smem);
    const int tid = threadIdx.x;
    const int lane = tid & 31;
    const int wid = tid >> 5;
    const int warp_m = wid & 3;       // 0..3 -> 64-row strip
    const int warp_n = wid >> 2;      // 0..1 -> 64-col strip
    const int grp = lane >> 2;
    const int tig = lane & 3;

    const int m_base = blockIdx.y * BM;
    const int n_base = blockIdx.x * BN;

    // --- ldmatrix per-lane base addresses (stage 0) ---
    const int lj = lane >> 3;         // matrix index 0..3
    const int lr = lane & 7;          // row within matrix
    // A: matrix j -> (m-half = j&1, k-half = j>>1); k-half = 8 bf16 = 16 B
    const uint32_t aH0 = sbase + AH_OFF
        + (uint32_t)((warp_m * 64 + (lj & 1) * 8 + lr) * ROWB + (lj >> 1) * 16);
    const uint32_t aL0 = aH0 + (AL_OFF - AH_OFF);
    // B: matrix j -> (n-sub = j>>1, k-half = j&1)
    const uint32_t bH0 = sbase + BH_OFF
        + (uint32_t)((warp_n * 64 + (lj >> 1) * 8 + lr) * ROWB + (lj & 1) * 16);
    const uint32_t bL0 = bH0 + (BL_OFF - BH_OFF);

    float acc[4][8][4];
    #pragma unroll
    for (int t = 0; t < 4; t++)
        #pragma unroll
        for (int j = 0; j < 8; j++)
            #pragma unroll
            for (int q = 0; q < 4; q++)
                acc[t][j][q] = 0.0f;

    auto produce = [&](int stage, int kb) {
        char* st = smem + stage * STAGE_BYTES;
        const size_t kel = (size_t)kb * BK;
        // A hi/lo: 256 rows x 4 chunks of 16B
        #pragma unroll
        for (int j = 0; j < 4; j++) {
            const int c = tid + 256 * j;     // 0..1023
            const int r = c >> 2, ch = c & 3;
            const size_t gsrc = (size_t)(m_base + r) * KDIM + kel + ch * 8;
            cp_async16(smem_u32(st + AH_OFF + r * ROWB + ch * 16), g_Ah + gsrc);
            cp_async16(smem_u32(st + AL_OFF + r * ROWB + ch * 16), g_Al + gsrc);
        }
        // B hi/lo: 128 rows x 4 chunks
        #pragma unroll
        for (int j = 0; j < 2; j++) {
            const int c = tid + 256 * j;     // 0..511
            const int r = c >> 2, ch = c & 3;
            const size_t gsrc = (size_t)(n_base + r) * KDIM + kel + ch * 8;
            cp_async16(smem_u32(st + BH_OFF + r * ROWB + ch * 16), g_Wh + gsrc);
            cp_async16(smem_u32(st + BL_OFF + r * ROWB + ch * 16), g_Wl + gsrc);
        }
    };

    // prologue: fill 2 of 3 stages
    produce(0, 0); cp_commit();
    produce(1, 1); cp_commit();

    int stage = 0;
    for (int it = 0; it < KITERS; ++it) {
        cp_wait1();
        __syncthreads();

        if (it + 2 < KITERS) {
            int ps = stage + 2; if (ps >= STAGES) ps -= STAGES;
            produce(ps, it + 2);
        }
        cp_commit();

        const uint32_t so = (uint32_t)(stage * STAGE_BYTES);

        #pragma unroll
        for (int ks = 0; ks < 2; ks++) {     // 2 x k16 = BK 32
            const uint32_t koff = so + ks * 32;   // 16 bf16 = 32 B
            uint32_t ah[4][4], al[4][4], bh[8][2], bl[8][2];

            // hi fragments
            #pragma unroll
            for (int t = 0; t < 4; t++)
                ldsm_x4(ah[t][0], ah[t][1], ah[t][2], ah[t][3],
                        aH0 + koff + (uint32_t)(t * 16 * ROWB));
            #pragma unroll
            for (int p = 0; p < 4; p++)
                ldsm_x4(bh[2 * p][0], bh[2 * p][1], bh[2 * p + 1][0], bh[2 * p + 1][1],
                        bH0 + koff + (uint32_t)(p * 16 * ROWB));
            // term 1: Ah * Bh
            #pragma unroll
            for (int t = 0; t < 4; t++)
                #pragma unroll
                for (int j = 0; j < 8; j++)
                    mma_bf16(acc[t][j], ah[t], bh[j]);

            // term 2: Al * Bh
            #pragma unroll
            for (int t = 0; t < 4; t++)
                ldsm_x4(al[t][0], al[t][1], al[t][2], al[t][3],
                        aL0 + koff + (uint32_t)(t * 16 * ROWB));
            #pragma unroll
            for (int t = 0; t < 4; t++)
                #pragma unroll
                for (int j = 0; j < 8; j++)
                    mma_bf16(acc[t][j], al[t], bh[j]);

            // term 3: Ah * Bl
            #pragma unroll
            for (int p = 0; p < 4; p++)
                ldsm_x4(bl[2 * p][0], bl[2 * p][1], bl[2 * p + 1][0], bl[2 * p + 1][1],
                        bL0 + koff + (uint32_t)(p * 16 * ROWB));
            #pragma unroll
            for (int t = 0; t < 4; t++)
                #pragma unroll
                for (int j = 0; j < 8; j++)
                    mma_bf16(acc[t][j], ah[t], bl[j]);
        }

        if (++stage == STAGES) stage = 0;
    }

    // epilogue: float2 stores (same C layout as m16n8k8)
    #pragma unroll
    for (int t = 0; t < 4; t++) {
        const int r0 = m_base + warp_m * 64 + t * 16 + grp;
        #pragma unroll
        for (int j = 0; j < 8; j++) {
            const int cg = n_base + warp_n * 64 + j * 8 + 2 * tig;
            float2 v0 = make_float2(acc[t][j][0], acc[t][j][1]);
            float2 v1 = make_float2(acc[t][j][2], acc[t][j][3]);
            *reinterpret_cast<float2*>(out + (size_t)r0 * NDIM + cg) = v0;
            *reinterpret_cast<float2*>(out + (size_t)(r0 + 8) * NDIM + cg) = v1;
        }
    }
}

// ------------------------------- launch --------------------------------------

extern "C" void kernel_launch(void* const* d_in, const int* in_sizes, int n_in,
                              void* d_out, int out_size) {
    const float* A = (const float*)d_in[0];   // [8,1024,4096] == [8192,4096]
    const float* W = (const float*)d_in[1];   // [4096,4096] (N,K)
    float* out = (float*)d_out;               // [8192,4096]
    (void)in_sizes; (void)n_in; (void)out_size;

    cudaFuncSetAttribute(gemm_kernel,
                         cudaFuncAttributeMaxDynamicSharedMemorySize, SMEM_TOTAL);

    prepass_kernel<<<1184, 256>>>(A, W);

    dim3 grid(NDIM / BN, MTOT / BM);   // (32, 32) = 1024 CTAs
    gemm_kernel<<<grid, 256, SMEM_TOTAL>>>(out);
}

// round 8
// speedup vs baseline: 2.2485x; 2.2485x over previous
#include <cuda_runtime.h>
#include <cuda_fp16.h>
#include <cstdint>

// ---------------------------------------------------------------------------
// C[8192,4096] = A[8192,4096] * W[4096,4096]^T  (fp32 in/out)
// R8: single-term fp16 GEMM. fp16 mantissa (10 bits) == tf32 mantissa, so
// precision matches the tf32 path (measured rel_err 2.9e-4) while using
// mma.sync.m16n8k16.f16 -> HALF the mma instruction count (the measured
// limiter: every mma.sync issues at ~12 cyc/SMSP regardless of shape).
// BM=256, BN=128, BK=32, 256 thr, warp tile 64x64, 4-stage cp.async,
// ldmatrix.x4 fragment loads.
// ---------------------------------------------------------------------------

#define MTOT 8192
#define KDIM 4096
#define NDIM 4096

#define BM 256
#define BN 128
#define BK 32
#define KITERS (KDIM / BK)        // 128
#define STAGES 4

// fp16 smem rows: 32 fp16 = 64B data padded to 80B per row.
// stride 80 mod 128 walk {0,80,32,112,64,16,96,48} -> ldmatrix conflict-free.
#define ROWB 80
#define A_OFF 0
#define B_OFF (BM * ROWB)                  // 20480
#define STAGE_BYTES ((BM + BN) * ROWB)     // 30720
#define SMEM_TOTAL (STAGES * STAGE_BYTES)  // 122880

// fp16 scratch copies (device globals: allowed, no allocation)
__device__ __half g_Ah[(size_t)MTOT * KDIM];
__device__ __half g_Wh[(size_t)NDIM * KDIM];

// ------------------------------- helpers -----------------------------------

__device__ __forceinline__ uint32_t smem_u32(const void* p) {
    uint32_t a;
    asm("{ .reg .u64 t; cvta.to.shared.u64 t, %1; cvt.u32.u64 %0, t; }"
        : "=r"(a) : "l"(p));
    return a;
}

__device__ __forceinline__ void cp_async16(uint32_t dst, const void* src) {
    asm volatile("cp.async.cg.shared.global [%0], [%1], 16;\n"
                 :: "r"(dst), "l"(src) : "memory");
}
__device__ __forceinline__ void cp_commit() {
    asm volatile("cp.async.commit_group;\n" ::: "memory");
}
__device__ __forceinline__ void cp_wait2() {
    asm volatile("cp.async.wait_group 2;\n" ::: "memory");
}

__device__ __forceinline__ void ldsm_x4(uint32_t& r0, uint32_t& r1,
                                        uint32_t& r2, uint32_t& r3,
                                        uint32_t addr) {
    asm volatile("ldmatrix.sync.aligned.m8n8.x4.shared.b16 {%0,%1,%2,%3}, [%4];"
                 : "=r"(r0), "=r"(r1), "=r"(r2), "=r"(r3) : "r"(addr));
}

__device__ __forceinline__ void mma_f16(float* c, const uint32_t* a,
                                        const uint32_t* b) {
    asm volatile(
        "mma.sync.aligned.m16n8k16.row.col.f32.f16.f16.f32 "
        "{%0,%1,%2,%3}, {%4,%5,%6,%7}, {%8,%9}, {%0,%1,%2,%3};"
        : "+f"(c[0]), "+f"(c[1]), "+f"(c[2]), "+f"(c[3])
        : "r"(a[0]), "r"(a[1]), "r"(a[2]), "r"(a[3]),
          "r"(b[0]), "r"(b[1]));
}

// ------------------------------- prepass ------------------------------------
// Convert A and W to fp16 (round-to-nearest). 10-bit mantissa == tf32;
// A ~ N(0,1) and W ~ N(0,4e-4) are fully in fp16 range.

__global__ void __launch_bounds__(256) prepass_kernel(const float* __restrict__ A,
                                                      const float* __restrict__ W) {
    const long long nA = (long long)MTOT * KDIM / 4;
    const long long nW = (long long)NDIM * KDIM / 4;
    const long long stride = (long long)gridDim.x * blockDim.x;
    for (long long i = (long long)blockIdx.x * blockDim.x + threadIdx.x;
         i < nA + nW; i += stride) {
        const float4* src;
        __half* dst;
        long long j;
        if (i < nA) { src = (const float4*)A; dst = g_Ah; j = i; }
        else        { src = (const float4*)W; dst = g_Wh; j = i - nA; }
        float4 v = src[j];
        __half2* p = (__half2*)(dst + 4 * j);
        p[0] = __floats2half2_rn(v.x, v.y);
        p[1] = __floats2half2_rn(v.z, v.w);
    }
}

// ------------------------------- GEMM ---------------------------------------

__global__ void __launch_bounds__(256, 1) gemm_kernel(float* __restrict__ out) {
    extern __shared__ char smem[];
    const uint32_t sbase = smem_u32(smem);
    const int tid = threadIdx.x;
    const int lane = tid & 31;
    const int wid = tid >> 5;
    const int warp_m = wid & 3;       // 0..3 -> 64-row strip
    const int warp_n = wid >> 2;      // 0..1 -> 64-col strip
    const int grp = lane >> 2;
    const int tig = lane & 3;

    const int m_base = blockIdx.y * BM;
    const int n_base = blockIdx.x * BN;

    // --- ldmatrix per-lane base addresses (stage 0) ---
    const int lj = lane >> 3;         // matrix index 0..3
    const int lr = lane & 7;          // row within matrix
    // A: matrix j -> (m-half = j&1, k-half = j>>1); k-half = 8 fp16 = 16 B
    const uint32_t a_lane = sbase + A_OFF
        + (uint32_t)((warp_m * 64 + (lj & 1) * 8 + lr) * ROWB + (lj >> 1) * 16);
    // B: matrix j -> (n-sub = j>>1, k-half = j&1)
    const uint32_t b_lane = sbase + B_OFF
        + (uint32_t)((warp_n * 64 + (lj >> 1) * 8 + lr) * ROWB + (lj & 1) * 16);

    float acc[4][8][4];
    #pragma unroll
    for (int t = 0; t < 4; t++)
        #pragma unroll
        for (int j = 0; j < 8; j++)
            #pragma unroll
            for (int q = 0; q < 4; q++)
                acc[t][j][q] = 0.0f;

    auto produce = [&](int stage, int kb) {
        char* st = smem + stage * STAGE_BYTES;
        const size_t kel = (size_t)kb * BK;
        // A: 256 rows x 4 chunks of 16B (8 fp16)
        #pragma unroll
        for (int j = 0; j < 4; j++) {
            const int c = tid + 256 * j;     // 0..1023
            const int r = c >> 2, ch = c & 3;
            cp_async16(smem_u32(st + A_OFF + r * ROWB + ch * 16),
                       g_Ah + (size_t)(m_base + r) * KDIM + kel + ch * 8);
        }
        // B: 128 rows x 4 chunks
        #pragma unroll
        for (int j = 0; j < 2; j++) {
            const int c = tid + 256 * j;     // 0..511
            const int r = c >> 2, ch = c & 3;
            cp_async16(smem_u32(st + B_OFF + r * ROWB + ch * 16),
                       g_Wh + (size_t)(n_base + r) * KDIM + kel + ch * 8);
        }
    };

    // prologue: fill 3 of 4 stages
    produce(0, 0); cp_commit();
    produce(1, 1); cp_commit();
    produce(2, 2); cp_commit();

    for (int it = 0; it < KITERS; ++it) {
        const int stage = it & 3;

        cp_wait2();          // stage `it` resident (<=2 groups pending)
        __syncthreads();     // all reads of stage it-1 done; safe to refill

        if (it + 3 < KITERS) produce((it + 3) & 3, it + 3);
        cp_commit();         // fixed group count per iteration

        const uint32_t so = (uint32_t)(stage * STAGE_BYTES);

        #pragma unroll
        for (int ks = 0; ks < 2; ks++) {     // 2 x k16 = BK 32
            const uint32_t koff = so + ks * 32;   // 16 fp16 = 32 B
            uint32_t a[4][4], b[8][2];
            #pragma unroll
            for (int t = 0; t < 4; t++)
                ldsm_x4(a[t][0], a[t][1], a[t][2], a[t][3],
                        a_lane + koff + (uint32_t)(t * 16 * ROWB));
            #pragma unroll
            for (int p = 0; p < 4; p++)
                ldsm_x4(b[2 * p][0], b[2 * p][1], b[2 * p + 1][0], b[2 * p + 1][1],
                        b_lane + koff + (uint32_t)(p * 16 * ROWB));
            #pragma unroll
            for (int t = 0; t < 4; t++)
                #pragma unroll
                for (int j = 0; j < 8; j++)
                    mma_f16(acc[t][j], a[t], b[j]);
        }
    }

    // epilogue: float2 stores (m16n8 C layout)
    #pragma unroll
    for (int t = 0; t < 4; t++) {
        const int r0 = m_base + warp_m * 64 + t * 16 + grp;
        #pragma unroll
        for (int j = 0; j < 8; j++) {
            const int cg = n_base + warp_n * 64 + j * 8 + 2 * tig;
            float2 v0 = make_float2(acc[t][j][0], acc[t][j][1]);
            float2 v1 = make_float2(acc[t][j][2], acc[t][j][3]);
            *reinterpret_cast<float2*>(out + (size_t)r0 * NDIM + cg) = v0;
            *reinterpret_cast<float2*>(out + (size_t)(r0 + 8) * NDIM + cg) = v1;
        }
    }
}

// ------------------------------- launch --------------------------------------

extern "C" void kernel_launch(void* const* d_in, const int* in_sizes, int n_in,
                              void* d_out, int out_size) {
    const float* A = (const float*)d_in[0];   // [8,1024,4096] == [8192,4096]
    const float* W = (const float*)d_in[1];   // [4096,4096] (N,K)
    float* out = (float*)d_out;               // [8192,4096]
    (void)in_sizes; (void)n_in; (void)out_size;

    cudaFuncSetAttribute(gemm_kernel,
                         cudaFuncAttributeMaxDynamicSharedMemorySize, SMEM_TOTAL);

    prepass_kernel<<<1184, 256>>>(A, W);

    dim3 grid(NDIM / BN, MTOT / BM);   // (32, 32) = 1024 CTAs
    gemm_kernel<<<grid, 256, SMEM_TOTAL>>>(out);
}

// round 9
// speedup vs baseline: 2.6840x; 1.1937x over previous
#include <cuda_runtime.h>
#include <cuda_fp16.h>
#include <cstdint>

// ---------------------------------------------------------------------------
// C[8192,4096] = A[8192,4096] * W[4096,4096]^T  (fp32 in/out)
// R9: fp16 m16n8k16 GEMM (fp16 mantissa == tf32 -> rel_err ~2.9e-4).
// vs R8: 512 threads (16 warps, 4/SMSP) to hide mma latency, BK=64 to halve
// barrier frequency, warp tile 32x64, 3-stage cp.async, ldmatrix.x4.
// ---------------------------------------------------------------------------

#define MTOT 8192
#define KDIM 4096
#define NDIM 4096

#define BM 256
#define BN 128
#define BK 64
#define KITERS (KDIM / BK)        // 64
#define STAGES 3

// fp16 smem rows: 64 fp16 = 128B data + 16B pad = 144B stride.
// 144 mod 128 walks {0,16,32,...,112} over 8 rows -> ldmatrix conflict-free.
#define ROWB 144
#define A_OFF 0
#define B_OFF (BM * ROWB)                  // 36864
#define STAGE_BYTES ((BM + BN) * ROWB)     // 55296
#define SMEM_TOTAL (STAGES * STAGE_BYTES)  // 165888

// fp16 scratch copies (device globals: allowed, no allocation)
__device__ __half g_Ah[(size_t)MTOT * KDIM];
__device__ __half g_Wh[(size_t)NDIM * KDIM];

// ------------------------------- helpers -----------------------------------

__device__ __forceinline__ uint32_t smem_u32(const void* p) {
    uint32_t a;
    asm("{ .reg .u64 t; cvta.to.shared.u64 t, %1; cvt.u32.u64 %0, t; }"
        : "=r"(a) : "l"(p));
    return a;
}

__device__ __forceinline__ void cp_async16(uint32_t dst, const void* src) {
    asm volatile("cp.async.cg.shared.global [%0], [%1], 16;\n"
                 :: "r"(dst), "l"(src) : "memory");
}
__device__ __forceinline__ void cp_commit() {
    asm volatile("cp.async.commit_group;\n" ::: "memory");
}
__device__ __forceinline__ void cp_wait1() {
    asm volatile("cp.async.wait_group 1;\n" ::: "memory");
}

__device__ __forceinline__ void ldsm_x4(uint32_t& r0, uint32_t& r1,
                                        uint32_t& r2, uint32_t& r3,
                                        uint32_t addr) {
    asm volatile("ldmatrix.sync.aligned.m8n8.x4.shared.b16 {%0,%1,%2,%3}, [%4];"
                 : "=r"(r0), "=r"(r1), "=r"(r2), "=r"(r3) : "r"(addr));
}

__device__ __forceinline__ void mma_f16(float* c, const uint32_t* a,
                                        const uint32_t* b) {
    asm volatile(
        "mma.sync.aligned.m16n8k16.row.col.f32.f16.f16.f32 "
        "{%0,%1,%2,%3}, {%4,%5,%6,%7}, {%8,%9}, {%0,%1,%2,%3};"
        : "+f"(c[0]), "+f"(c[1]), "+f"(c[2]), "+f"(c[3])
        : "r"(a[0]), "r"(a[1]), "r"(a[2]), "r"(a[3]),
          "r"(b[0]), "r"(b[1]));
}

// ------------------------------- prepass ------------------------------------

__global__ void __launch_bounds__(256) prepass_kernel(const float* __restrict__ A,
                                                      const float* __restrict__ W) {
    const long long nA = (long long)MTOT * KDIM / 4;
    const long long nW = (long long)NDIM * KDIM / 4;
    const long long stride = (long long)gridDim.x * blockDim.x;
    for (long long i = (long long)blockIdx.x * blockDim.x + threadIdx.x;
         i < nA + nW; i += stride) {
        const float4* src;
        __half* dst;
        long long j;
        if (i < nA) { src = (const float4*)A; dst = g_Ah; j = i; }
        else        { src = (const float4*)W; dst = g_Wh; j = i - nA; }
        float4 v = src[j];
        __half2* p = (__half2*)(dst + 4 * j);
        p[0] = __floats2half2_rn(v.x, v.y);
        p[1] = __floats2half2_rn(v.z, v.w);
    }
}

// ------------------------------- GEMM ---------------------------------------

__global__ void __launch_bounds__(512, 1) gemm_kernel(float* __restrict__ out) {
    extern __shared__ char smem[];
    const uint32_t sbase = smem_u32(smem);
    const int tid = threadIdx.x;
    const int lane = tid & 31;
    const int wid = tid >> 5;
    const int warp_m = wid >> 1;      // 0..7 -> 32-row strip
    const int warp_n = wid & 1;       // 0..1 -> 64-col strip
    const int grp = lane >> 2;
    const int tig = lane & 3;

    const int m_base = blockIdx.y * BM;
    const int n_base = blockIdx.x * BN;

    // --- ldmatrix per-lane base addresses (stage 0) ---
    const int lj = lane >> 3;         // matrix index 0..3
    const int lr = lane & 7;          // row within matrix
    // A: matrix j -> (m-half = j&1, k-half = j>>1); k-half = 8 fp16 = 16 B
    const uint32_t a_lane = sbase + A_OFF
        + (uint32_t)((warp_m * 32 + (lj & 1) * 8 + lr) * ROWB + (lj >> 1) * 16);
    // B: matrix j -> (n-sub = j>>1, k-half = j&1)
    const uint32_t b_lane = sbase + B_OFF
        + (uint32_t)((warp_n * 64 + (lj >> 1) * 8 + lr) * ROWB + (lj & 1) * 16);

    float acc[2][8][4];
    #pragma unroll
    for (int t = 0; t < 2; t++)
        #pragma unroll
        for (int j = 0; j < 8; j++)
            #pragma unroll
            for (int q = 0; q < 4; q++)
                acc[t][j][q] = 0.0f;

    auto produce = [&](int stage, int kb) {
        char* st = smem + stage * STAGE_BYTES;
        const size_t kel = (size_t)kb * BK;
        // A: 256 rows x 8 chunks of 16B (8 fp16 each)
        #pragma unroll
        for (int j = 0; j < 4; j++) {
            const int c = tid + 512 * j;     // 0..2047
            const int r = c >> 3, ch = c & 7;
            cp_async16(smem_u32(st + A_OFF + r * ROWB + ch * 16),
                       g_Ah + (size_t)(m_base + r) * KDIM + kel + ch * 8);
        }
        // B: 128 rows x 8 chunks
        #pragma unroll
        for (int j = 0; j < 2; j++) {
            const int c = tid + 512 * j;     // 0..1023
            const int r = c >> 3, ch = c & 7;
            cp_async16(smem_u32(st + B_OFF + r * ROWB + ch * 16),
                       g_Wh + (size_t)(n_base + r) * KDIM + kel + ch * 8);
        }
    };

    // prologue: fill 2 of 3 stages
    produce(0, 0); cp_commit();
    produce(1, 1); cp_commit();

    int stage = 0;
    for (int it = 0; it < KITERS; ++it) {
        cp_wait1();
        __syncthreads();

        if (it + 2 < KITERS) {
            int ps = stage + 2; if (ps >= STAGES) ps -= STAGES;
            produce(ps, it + 2);
        }
        cp_commit();

        const uint32_t so = (uint32_t)(stage * STAGE_BYTES);

        #pragma unroll
        for (int ks = 0; ks < 4; ks++) {      // 4 x k16 = BK 64
            const uint32_t koff = so + ks * 32;   // 16 fp16 = 32 B
            uint32_t a[2][4], b[8][2];
            #pragma unroll
            for (int t = 0; t < 2; t++)
                ldsm_x4(a[t][0], a[t][1], a[t][2], a[t][3],
                        a_lane + koff + (uint32_t)(t * 16 * ROWB));
            #pragma unroll
            for (int p = 0; p < 4; p++)
                ldsm_x4(b[2 * p][0], b[2 * p][1], b[2 * p + 1][0], b[2 * p + 1][1],
                        b_lane + koff + (uint32_t)(p * 16 * ROWB));
            #pragma unroll
            for (int t = 0; t < 2; t++)
                #pragma unroll
                for (int j = 0; j < 8; j++)
                    mma_f16(acc[t][j], a[t], b[j]);
        }

        if (++stage == STAGES) stage = 0;
    }

    // epilogue: float2 stores (m16n8 C layout)
    #pragma unroll
    for (int t = 0; t < 2; t++) {
        const int r0 = m_base + warp_m * 32 + t * 16 + grp;
        #pragma unroll
        for (int j = 0; j < 8; j++) {
            const int cg = n_base + warp_n * 64 + j * 8 + 2 * tig;
            float2 v0 = make_float2(acc[t][j][0], acc[t][j][1]);
            float2 v1 = make_float2(acc[t][j][2], acc[t][j][3]);
            *reinterpret_cast<float2*>(out + (size_t)r0 * NDIM + cg) = v0;
            *reinterpret_cast<float2*>(out + (size_t)(r0 + 8) * NDIM + cg) = v1;
        }
    }
}

// ------------------------------- launch --------------------------------------

extern "C" void kernel_launch(void* const* d_in, const int* in_sizes, int n_in,
                              void* d_out, int out_size) {
    const float* A = (const float*)d_in[0];   // [8,1024,4096] == [8192,4096]
    const float* W = (const float*)d_in[1];   // [4096,4096] (N,K)
    float* out = (float*)d_out;               // [8192,4096]
    (void)in_sizes; (void)n_in; (void)out_size;

    cudaFuncSetAttribute(gemm_kernel,
                         cudaFuncAttributeMaxDynamicSharedMemorySize, SMEM_TOTAL);

    prepass_kernel<<<1184, 256>>>(A, W);

    dim3 grid(NDIM / BN, MTOT / BM);   // (32, 32) = 1024 CTAs
    gemm_kernel<<<grid, 512, SMEM_TOTAL>>>(out);
}

// round 10
// speedup vs baseline: 2.8211x; 1.0511x over previous
#include <cuda_runtime.h>
#include <cuda_fp16.h>
#include <cstdint>

// ---------------------------------------------------------------------------
// C[8192,4096] = A[8192,4096] * W[4096,4096]^T  (fp32 in/out)
// R10: fp16 m16n8k16 GEMM (fp16 mantissa == tf32 -> rel_err ~2.9e-4).
// vs R9: 2 CTAs/SM (256 thr each, BM=128) so barrier domains decouple and
// the tensor pipe keeps issuing while the sibling CTA syncs.
// BM=128, BN=128, BK=64, warp tile 32x64, 3-stage cp.async, ldmatrix.x4.
// ---------------------------------------------------------------------------

#define MTOT 8192
#define KDIM 4096
#define NDIM 4096

#define BM 128
#define BN 128
#define BK 64
#define KITERS (KDIM / BK)        // 64
#define STAGES 3

// fp16 smem rows: 64 fp16 = 128B data + 16B pad = 144B stride.
// 144 mod 128 walks {0,16,...,112} over 8 rows -> ldmatrix conflict-free.
#define ROWB 144
#define A_OFF 0
#define B_OFF (BM * ROWB)                  // 18432
#define STAGE_BYTES ((BM + BN) * ROWB)     // 36864
#define SMEM_TOTAL (STAGES * STAGE_BYTES)  // 110592  (x2 CTAs = 221184/SM)

// fp16 scratch copies (device globals: allowed, no allocation)
__device__ __half g_Ah[(size_t)MTOT * KDIM];
__device__ __half g_Wh[(size_t)NDIM * KDIM];

// ------------------------------- helpers -----------------------------------

__device__ __forceinline__ uint32_t smem_u32(const void* p) {
    uint32_t a;
    asm("{ .reg .u64 t; cvta.to.shared.u64 t, %1; cvt.u32.u64 %0, t; }"
        : "=r"(a) : "l"(p));
    return a;
}

__device__ __forceinline__ void cp_async16(uint32_t dst, const void* src) {
    asm volatile("cp.async.cg.shared.global [%0], [%1], 16;\n"
                 :: "r"(dst), "l"(src) : "memory");
}
__device__ __forceinline__ void cp_commit() {
    asm volatile("cp.async.commit_group;\n" ::: "memory");
}
__device__ __forceinline__ void cp_wait1() {
    asm volatile("cp.async.wait_group 1;\n" ::: "memory");
}

__device__ __forceinline__ void ldsm_x4(uint32_t& r0, uint32_t& r1,
                                        uint32_t& r2, uint32_t& r3,
                                        uint32_t addr) {
    asm volatile("ldmatrix.sync.aligned.m8n8.x4.shared.b16 {%0,%1,%2,%3}, [%4];"
                 : "=r"(r0), "=r"(r1), "=r"(r2), "=r"(r3) : "r"(addr));
}

__device__ __forceinline__ void mma_f16(float* c, const uint32_t* a,
                                        const uint32_t* b) {
    asm volatile(
        "mma.sync.aligned.m16n8k16.row.col.f32.f16.f16.f32 "
        "{%0,%1,%2,%3}, {%4,%5,%6,%7}, {%8,%9}, {%0,%1,%2,%3};"
        : "+f"(c[0]), "+f"(c[1]), "+f"(c[2]), "+f"(c[3])
        : "r"(a[0]), "r"(a[1]), "r"(a[2]), "r"(a[3]),
          "r"(b[0]), "r"(b[1]));
}

// ------------------------------- prepass ------------------------------------

__global__ void __launch_bounds__(256) prepass_kernel(const float* __restrict__ A,
                                                      const float* __restrict__ W) {
    const long long nA = (long long)MTOT * KDIM / 4;
    const long long nW = (long long)NDIM * KDIM / 4;
    const long long stride = (long long)gridDim.x * blockDim.x;
    for (long long i = (long long)blockIdx.x * blockDim.x + threadIdx.x;
         i < nA + nW; i += stride) {
        const float4* src;
        __half* dst;
        long long j;
        if (i < nA) { src = (const float4*)A; dst = g_Ah; j = i; }
        else        { src = (const float4*)W; dst = g_Wh; j = i - nA; }
        float4 v = src[j];
        __half2* p = (__half2*)(dst + 4 * j);
        p[0] = __floats2half2_rn(v.x, v.y);
        p[1] = __floats2half2_rn(v.z, v.w);
    }
}

// ------------------------------- GEMM ---------------------------------------

__global__ void __launch_bounds__(256, 2) gemm_kernel(float* __restrict__ out) {
    extern __shared__ char smem[];
    const uint32_t sbase = smem_u32(smem);
    const int tid = threadIdx.x;
    const int lane = tid & 31;
    const int wid = tid >> 5;
    const int warp_m = wid & 3;       // 0..3 -> 32-row strip
    const int warp_n = wid >> 2;      // 0..1 -> 64-col strip
    const int grp = lane >> 2;
    const int tig = lane & 3;

    const int m_base = blockIdx.y * BM;
    const int n_base = blockIdx.x * BN;

    // --- ldmatrix per-lane base addresses (stage 0) ---
    const int lj = lane >> 3;         // matrix index 0..3
    const int lr = lane & 7;          // row within matrix
    // A: matrix j -> (m-half = j&1, k-half = j>>1); k-half = 8 fp16 = 16 B
    const uint32_t a_lane = sbase + A_OFF
        + (uint32_t)((warp_m * 32 + (lj & 1) * 8 + lr) * ROWB + (lj >> 1) * 16);
    // B: matrix j -> (n-sub = j>>1, k-half = j&1)
    const uint32_t b_lane = sbase + B_OFF
        + (uint32_t)((warp_n * 64 + (lj >> 1) * 8 + lr) * ROWB + (lj & 1) * 16);

    float acc[2][8][4];
    #pragma unroll
    for (int t = 0; t < 2; t++)
        #pragma unroll
        for (int j = 0; j < 8; j++)
            #pragma unroll
            for (int q = 0; q < 4; q++)
                acc[t][j][q] = 0.0f;

    auto produce = [&](int stage, int kb) {
        char* st = smem + stage * STAGE_BYTES;
        const size_t kel = (size_t)kb * BK;
        // A: 128 rows x 8 chunks of 16B (8 fp16 each) = 1024 chunks
        #pragma unroll
        for (int j = 0; j < 4; j++) {
            const int c = tid + 256 * j;     // 0..1023
            const int r = c >> 3, ch = c & 7;
            cp_async16(smem_u32(st + A_OFF + r * ROWB + ch * 16),
                       g_Ah + (size_t)(m_base + r) * KDIM + kel + ch * 8);
        }
        // B: 128 rows x 8 chunks = 1024 chunks
        #pragma unroll
        for (int j = 0; j < 4; j++) {
            const int c = tid + 256 * j;     // 0..1023
            const int r = c >> 3, ch = c & 7;
            cp_async16(smem_u32(st + B_OFF + r * ROWB + ch * 16),
                       g_Wh + (size_t)(n_base + r) * KDIM + kel + ch * 8);
        }
    };

    // prologue: fill 2 of 3 stages
    produce(0, 0); cp_commit();
    produce(1, 1); cp_commit();

    int stage = 0;
    for (int it = 0; it < KITERS; ++it) {
        cp_wait1();
        __syncthreads();

        if (it + 2 < KITERS) {
            int ps = stage + 2; if (ps >= STAGES) ps -= STAGES;
            produce(ps, it + 2);
        }
        cp_commit();

        const uint32_t so = (uint32_t)(stage * STAGE_BYTES);

        #pragma unroll
        for (int ks = 0; ks < 4; ks++) {      // 4 x k16 = BK 64
            const uint32_t koff = so + ks * 32;   // 16 fp16 = 32 B
            uint32_t a[2][4], b[8][2];
            #pragma unroll
            for (int t = 0; t < 2; t++)
                ldsm_x4(a[t][0], a[t][1], a[t][2], a[t][3],
                        a_lane + koff + (uint32_t)(t * 16 * ROWB));
            #pragma unroll
            for (int p = 0; p < 4; p++)
                ldsm_x4(b[2 * p][0], b[2 * p][1], b[2 * p + 1][0], b[2 * p + 1][1],
                        b_lane + koff + (uint32_t)(p * 16 * ROWB));
            #pragma unroll
            for (int t = 0; t < 2; t++)
                #pragma unroll
                for (int j = 0; j < 8; j++)
                    mma_f16(acc[t][j], a[t], b[j]);
        }

        if (++stage == STAGES) stage = 0;
    }

    // epilogue: float2 stores (m16n8 C layout)
    #pragma unroll
    for (int t = 0; t < 2; t++) {
        const int r0 = m_base + warp_m * 32 + t * 16 + grp;
        #pragma unroll
        for (int j = 0; j < 8; j++) {
            const int cg = n_base + warp_n * 64 + j * 8 + 2 * tig;
            float2 v0 = make_float2(acc[t][j][0], acc[t][j][1]);
            float2 v1 = make_float2(acc[t][j][2], acc[t][j][3]);
            *reinterpret_cast<float2*>(out + (size_t)r0 * NDIM + cg) = v0;
            *reinterpret_cast<float2*>(out + (size_t)(r0 + 8) * NDIM + cg) = v1;
        }
    }
}

// ------------------------------- launch --------------------------------------

extern "C" void kernel_launch(void* const* d_in, const int* in_sizes, int n_in,
                              void* d_out, int out_size) {
    const float* A = (const float*)d_in[0];   // [8,1024,4096] == [8192,4096]
    const float* W = (const float*)d_in[1];   // [4096,4096] (N,K)
    float* out = (float*)d_out;               // [8192,4096]
    (void)in_sizes; (void)n_in; (void)out_size;

    cudaFuncSetAttribute(gemm_kernel,
                         cudaFuncAttributeMaxDynamicSharedMemorySize, SMEM_TOTAL);

    prepass_kernel<<<1184, 256>>>(A, W);

    dim3 grid(NDIM / BN, MTOT / BM);   // (32, 64) = 2048 CTAs
    gemm_kernel<<<grid, 256, SMEM_TOTAL>>>(out);
}